// round 3
// baseline (speedup 1.0000x reference)
#include <cuda_runtime.h>
#include <cuda_bf16.h>
#include <cstdint>
#include <math.h>

#define N 8192
#define D 1024
#define BM 128
#define BN 128
#define BK 64
#define STAGES 4
#define THREADS 256
#define TILES 32                  // j-tiles per CTA (half of 8192 / BN)
#define KCHUNKS (D / BK)          // 16
#define TOTCH (TILES * KCHUNKS)   // 512

#define STAGE_BYTES 32768         // A 16KB + B 16KB, SW128 layout
#define SMEM_TOTAL (STAGES * STAGE_BYTES)   // 131072

// device scratch
__device__ __nv_bfloat16 g_Rb[(long)N * D];
__device__ __nv_bfloat16 g_Lb[(long)N * D];
__device__ float g_pm[4 * N];   // 4 partials per row: (half,wn)
__device__ float g_ps[4 * N];
__device__ float g_diag[N];

// ---------------------------------------------------------------------------
// helpers
// ---------------------------------------------------------------------------
__device__ __forceinline__ uint32_t smem_u32(const void* p) {
    uint32_t a;
    asm("{ .reg .u64 t; cvta.to.shared.u64 t, %1; cvt.u32.u64 %0, t; }" : "=r"(a) : "l"(p));
    return a;
}
__device__ __forceinline__ void cp16(uint32_t saddr, const void* g) {
    asm volatile("cp.async.cg.shared.global [%0],[%1],16;\n" :: "r"(saddr), "l"(g));
}
__device__ __forceinline__ void ldsm4(uint32_t* r, uint32_t addr) {
    asm volatile("ldmatrix.sync.aligned.m8n8.x4.shared.b16 {%0,%1,%2,%3}, [%4];"
                 : "=r"(r[0]), "=r"(r[1]), "=r"(r[2]), "=r"(r[3]) : "r"(addr));
}
__device__ __forceinline__ void mma16816(float* c, const uint32_t* a, uint32_t b0, uint32_t b1) {
    asm volatile(
        "mma.sync.aligned.m16n8k16.row.col.f32.bf16.bf16.f32 "
        "{%0,%1,%2,%3},{%4,%5,%6,%7},{%8,%9},{%0,%1,%2,%3};"
        : "+f"(c[0]), "+f"(c[1]), "+f"(c[2]), "+f"(c[3])
        : "r"(a[0]), "r"(a[1]), "r"(a[2]), "r"(a[3]), "r"(b0), "r"(b1));
}
__device__ __forceinline__ float ex2f(float x) {
    float r;
    asm("ex2.approx.ftz.f32 %0, %1;" : "=f"(r) : "f"(x));
    return r;
}

// ---------------------------------------------------------------------------
// Kernel 1: fp32 -> bf16 conversion
// ---------------------------------------------------------------------------
__global__ void convert_kernel(const float* __restrict__ R, const float* __restrict__ L) {
    long i = ((long)blockIdx.x * blockDim.x + threadIdx.x) * 4;
    if (i >= (long)N * D) return;
    float4 r = *(const float4*)(R + i);
    float4 l = *(const float4*)(L + i);
    *(__nv_bfloat162*)(g_Rb + i)     = __floats2bfloat162_rn(r.x, r.y);
    *(__nv_bfloat162*)(g_Rb + i + 2) = __floats2bfloat162_rn(r.z, r.w);
    *(__nv_bfloat162*)(g_Lb + i)     = __floats2bfloat162_rn(l.x, l.y);
    *(__nv_bfloat162*)(g_Lb + i + 2) = __floats2bfloat162_rn(l.z, l.w);
}

// ---------------------------------------------------------------------------
// Kernel 2: exact fp32 diagonal dot products
// ---------------------------------------------------------------------------
__global__ void diag_kernel(const float* __restrict__ R, const float* __restrict__ L) {
    int row  = blockIdx.x * 8 + (threadIdx.x >> 5);
    int lane = threadIdx.x & 31;
    const float* r = R + (long)row * D;
    const float* l = L + (long)row * D;
    float s = 0.f;
    #pragma unroll 8
    for (int k = lane; k < D; k += 32) s += r[k] * l[k];
    #pragma unroll
    for (int o = 16; o > 0; o >>= 1) s += __shfl_xor_sync(0xffffffffu, s, o);
    if (lane == 0) g_diag[row] = s;
}

// ---------------------------------------------------------------------------
// Kernel 3: mma.sync GEMM + register-resident online LSE
// ---------------------------------------------------------------------------
__device__ __forceinline__ void load_chunk(uint32_t sb, int g, int rowBase, long colBase0, int tid) {
    const int t = g >> 4, kc = g & 15, st = g & 3;
    const __nv_bfloat16* Asrc = g_Rb + (long)rowBase * D + kc * BK;
    const __nv_bfloat16* Bsrc = g_Lb + (colBase0 + (long)t * BN) * D + kc * BK;
    const uint32_t Ab = sb + st * STAGE_BYTES;
    const uint32_t Bb = Ab + 16384;
    #pragma unroll
    for (int i = 0; i < 4; i++) {
        int idx = i * THREADS + tid;              // 0..1023
        int row = idx >> 3, c = idx & 7;
        uint32_t off = row * 128 + c * 16;
        uint32_t sw = off ^ ((off >> 3) & 0x70);
        cp16(Ab + sw, Asrc + (long)row * D + c * 8);
    }
    #pragma unroll
    for (int i = 0; i < 4; i++) {
        int idx = i * THREADS + tid;
        int row = idx >> 3, c = idx & 7;
        uint32_t off = row * 128 + c * 16;
        uint32_t sw = off ^ ((off >> 3) & 0x70);
        cp16(Bb + sw, Bsrc + (long)row * D + c * 8);
    }
}

__global__ void __launch_bounds__(THREADS, 1) lse_kernel() {
    extern __shared__ char smem[];
    const uint32_t sb = smem_u32(smem);
    const int tid = threadIdx.x, wid = tid >> 5, lane = tid & 31;
    const int wm = wid >> 1, wn = wid & 1;       // 4x2 warp grid, 32x64 per warp
    const int rowBase = (blockIdx.x >> 1) * BM;
    const int half = blockIdx.x & 1;
    const long colBase0 = (long)half * (TILES * BN);
    const float LOG2E = 1.4426950408889634f;

    // per-lane ldmatrix source geometry
    const int q = lane >> 3, j = lane & 7;
    uint32_t aoff[2], asw[2];                    // per mi (m16 tile)
    #pragma unroll
    for (int mi = 0; mi < 2; mi++) {
        int row = wm * 32 + mi * 16 + (q & 1) * 8 + j;
        aoff[mi] = row * 128;
        asw[mi] = (row & 7) << 4;
    }
    const uint32_t axk = (q >> 1) * 16;          // k-half selector for A
    uint32_t boff[4], bsw[4];                    // per np (n16 pair)
    #pragma unroll
    for (int np = 0; np < 4; np++) {
        int row = wn * 64 + np * 16 + (q >> 1) * 8 + j;
        boff[np] = row * 128;
        bsw[np] = (row & 7) << 4;
    }
    const uint32_t bxk = (q & 1) * 16;           // k-half selector for B

    float c[2][8][4];
    #pragma unroll
    for (int mi = 0; mi < 2; mi++)
        #pragma unroll
        for (int ni = 0; ni < 8; ni++)
            #pragma unroll
            for (int qq = 0; qq < 4; qq++) c[mi][ni][qq] = 0.f;

    float st_m[2][2], st_s[2][2];                // [mi][h] online LSE state
    #pragma unroll
    for (int mi = 0; mi < 2; mi++)
        #pragma unroll
        for (int h = 0; h < 2; h++) { st_m[mi][h] = -INFINITY; st_s[mi][h] = 0.f; }

    // prologue: stage chunks 0..2
    load_chunk(sb, 0, rowBase, colBase0, tid);
    asm volatile("cp.async.commit_group;");
    load_chunk(sb, 1, rowBase, colBase0, tid);
    asm volatile("cp.async.commit_group;");
    load_chunk(sb, 2, rowBase, colBase0, tid);
    asm volatile("cp.async.commit_group;");

    for (int g = 0; g < TOTCH; ++g) {
        asm volatile("cp.async.wait_group 2;");
        __syncthreads();

        const int st = g & 3;
        const uint32_t Ast = sb + st * STAGE_BYTES;
        const uint32_t Bst = Ast + 16384;
        #pragma unroll
        for (int kk = 0; kk < 4; ++kk) {
            const uint32_t kx = kk * 32;
            uint32_t a[2][4], b[4][4];
            #pragma unroll
            for (int mi = 0; mi < 2; mi++)
                ldsm4(a[mi], Ast + aoff[mi] + (((kx + axk)) ^ asw[mi]));
            #pragma unroll
            for (int np = 0; np < 4; np++)
                ldsm4(b[np], Bst + boff[np] + (((kx + bxk)) ^ bsw[np]));
            #pragma unroll
            for (int mi = 0; mi < 2; mi++)
                #pragma unroll
                for (int ni = 0; ni < 8; ni++) {
                    const int np = ni >> 1, lo = ni & 1;
                    mma16816(c[mi][ni], a[mi], b[np][lo * 2], b[np][lo * 2 + 1]);
                }
        }

        if ((g & 15) == 15) {
            // ---- per-tile online LSE update, all in registers ----
            #pragma unroll
            for (int mi = 0; mi < 2; mi++)
                #pragma unroll
                for (int h = 0; h < 2; h++) {
                    float mx = fmaxf(c[mi][0][2 * h], c[mi][0][2 * h + 1]);
                    #pragma unroll
                    for (int ni = 1; ni < 8; ni++)
                        mx = fmaxf(mx, fmaxf(c[mi][ni][2 * h], c[mi][ni][2 * h + 1]));
                    mx = fmaxf(mx, __shfl_xor_sync(0xffffffffu, mx, 1));
                    mx = fmaxf(mx, __shfl_xor_sync(0xffffffffu, mx, 2));
                    const float nm = fmaxf(st_m[mi][h], mx);
                    const float nb = -nm * LOG2E;
                    float s0 = 0.f, s1 = 0.f;
                    #pragma unroll
                    for (int ni = 0; ni < 8; ni++) {
                        s0 += ex2f(fmaf(c[mi][ni][2 * h],     LOG2E, nb));
                        s1 += ex2f(fmaf(c[mi][ni][2 * h + 1], LOG2E, nb));
                    }
                    float sum = s0 + s1;
                    sum += __shfl_xor_sync(0xffffffffu, sum, 1);
                    sum += __shfl_xor_sync(0xffffffffu, sum, 2);
                    st_s[mi][h] = st_s[mi][h] * ex2f(fmaf(st_m[mi][h], LOG2E, nb)) + sum;
                    st_m[mi][h] = nm;
                }
            #pragma unroll
            for (int mi = 0; mi < 2; mi++)
                #pragma unroll
                for (int ni = 0; ni < 8; ni++)
                    #pragma unroll
                    for (int qq = 0; qq < 4; qq++) c[mi][ni][qq] = 0.f;
        }

        if (g + 3 < TOTCH) load_chunk(sb, g + 3, rowBase, colBase0, tid);
        asm volatile("cp.async.commit_group;");
    }

    // final per-row partial write (lane tg==0 of each quad)
    if ((lane & 3) == 0) {
        const int part = half * 2 + wn;
        #pragma unroll
        for (int mi = 0; mi < 2; mi++)
            #pragma unroll
            for (int h = 0; h < 2; h++) {
                int row = rowBase + wm * 32 + mi * 16 + h * 8 + (lane >> 2);
                g_pm[part * N + row] = st_m[mi][h];
                g_ps[part * N + row] = st_s[mi][h];
            }
    }
}

// ---------------------------------------------------------------------------
// Kernel 4: merge 4 partials per row, reduce to the scalar
// ---------------------------------------------------------------------------
__global__ void finalize_kernel(float* __restrict__ out) {
    __shared__ double red[256];
    double acc = 0.0;
    for (int i = threadIdx.x; i < N; i += 256) {
        float m0 = g_pm[i],         s0 = g_ps[i];
        float m1 = g_pm[N + i],     s1 = g_ps[N + i];
        float m2 = g_pm[2 * N + i], s2 = g_ps[2 * N + i];
        float m3 = g_pm[3 * N + i], s3 = g_ps[3 * N + i];
        float mm = fmaxf(fmaxf(m0, m1), fmaxf(m2, m3));
        float ss = s0 * __expf(m0 - mm) + s1 * __expf(m1 - mm) +
                   s2 * __expf(m2 - mm) + s3 * __expf(m3 - mm);
        double lse = (double)mm + log((double)ss);
        acc += lse - (double)g_diag[i];
    }
    red[threadIdx.x] = acc;
    __syncthreads();
    for (int s = 128; s > 0; s >>= 1) {
        if (threadIdx.x < s) red[threadIdx.x] += red[threadIdx.x + s];
        __syncthreads();
    }
    if (threadIdx.x == 0) out[0] = (float)(red[0] / (double)N);
}

// ---------------------------------------------------------------------------
extern "C" void kernel_launch(void* const* d_in, const int* in_sizes, int n_in,
                              void* d_out, int out_size) {
    const float* R = (const float*)d_in[0];   // rpr_r [N, D]
    const float* L = (const float*)d_in[1];   // rpr_l [N, D]
    float* out = (float*)d_out;

    cudaFuncSetAttribute(lse_kernel, cudaFuncAttributeMaxDynamicSharedMemorySize, SMEM_TOTAL);

    convert_kernel<<<(int)(((long)N * D / 4) / 256), 256>>>(R, L);
    diag_kernel<<<N / 8, 256>>>(R, L);
    lse_kernel<<<(N / BM) * 2, THREADS, SMEM_TOTAL>>>();
    finalize_kernel<<<1, 256>>>(out);
}

// round 4
// speedup vs baseline: 1.8173x; 1.8173x over previous
#include <cuda_runtime.h>
#include <cuda_fp16.h>
#include <cstdint>
#include <math.h>

#define N 8192
#define D 1024
#define BM 128
#define BN 128
#define BK 64
#define STAGES 4
#define THREADS 256
#define TILES 32                  // j-tiles per CTA (half of 8192 / BN)
#define KCHUNKS (D / BK)          // 16
#define TOTCH (TILES * KCHUNKS)   // 512

#define STAGE_BYTES 32768         // A 16KB + B 16KB, SW128 layout
#define SMEM_TOTAL (STAGES * STAGE_BYTES)   // 131072

// device scratch
__device__ __half g_Rh[(long)N * D];
__device__ __half g_Lh[(long)N * D];
__device__ float g_pm[4 * N];   // 4 partials per row: (half,wn)
__device__ float g_ps[4 * N];
__device__ float g_diag[N];

// ---------------------------------------------------------------------------
// helpers
// ---------------------------------------------------------------------------
__device__ __forceinline__ uint32_t smem_u32(const void* p) {
    uint32_t a;
    asm("{ .reg .u64 t; cvta.to.shared.u64 t, %1; cvt.u32.u64 %0, t; }" : "=r"(a) : "l"(p));
    return a;
}
__device__ __forceinline__ void cp16(uint32_t saddr, const void* g) {
    asm volatile("cp.async.cg.shared.global [%0],[%1],16;\n" :: "r"(saddr), "l"(g));
}
__device__ __forceinline__ void ldsm4(uint32_t* r, uint32_t addr) {
    asm volatile("ldmatrix.sync.aligned.m8n8.x4.shared.b16 {%0,%1,%2,%3}, [%4];"
                 : "=r"(r[0]), "=r"(r[1]), "=r"(r[2]), "=r"(r[3]) : "r"(addr));
}
// fp16 accumulate MMA: D(f16x2 pair) = A(f16) * B(f16) + D
__device__ __forceinline__ void mma16816h(uint32_t* c, const uint32_t* a, uint32_t b0, uint32_t b1) {
    asm volatile(
        "mma.sync.aligned.m16n8k16.row.col.f16.f16.f16.f16 "
        "{%0,%1},{%2,%3,%4,%5},{%6,%7},{%0,%1};"
        : "+r"(c[0]), "+r"(c[1])
        : "r"(a[0]), "r"(a[1]), "r"(a[2]), "r"(a[3]), "r"(b0), "r"(b1));
}
__device__ __forceinline__ float ex2f(float x) {
    float r;
    asm("ex2.approx.ftz.f32 %0, %1;" : "=f"(r) : "f"(x));
    return r;
}

// ---------------------------------------------------------------------------
// Kernel 1: fp32 -> fp16 conversion
// ---------------------------------------------------------------------------
__global__ void convert_kernel(const float* __restrict__ R, const float* __restrict__ L) {
    long i = ((long)blockIdx.x * blockDim.x + threadIdx.x) * 4;
    if (i >= (long)N * D) return;
    float4 r = *(const float4*)(R + i);
    float4 l = *(const float4*)(L + i);
    *(__half2*)(g_Rh + i)     = __floats2half2_rn(r.x, r.y);
    *(__half2*)(g_Rh + i + 2) = __floats2half2_rn(r.z, r.w);
    *(__half2*)(g_Lh + i)     = __floats2half2_rn(l.x, l.y);
    *(__half2*)(g_Lh + i + 2) = __floats2half2_rn(l.z, l.w);
}

// ---------------------------------------------------------------------------
// Kernel 2: exact fp32 diagonal dot products
// ---------------------------------------------------------------------------
__global__ void diag_kernel(const float* __restrict__ R, const float* __restrict__ L) {
    int row  = blockIdx.x * 8 + (threadIdx.x >> 5);
    int lane = threadIdx.x & 31;
    const float* r = R + (long)row * D;
    const float* l = L + (long)row * D;
    float s = 0.f;
    #pragma unroll 8
    for (int k = lane; k < D; k += 32) s += r[k] * l[k];
    #pragma unroll
    for (int o = 16; o > 0; o >>= 1) s += __shfl_xor_sync(0xffffffffu, s, o);
    if (lane == 0) g_diag[row] = s;
}

// dummy launch: shifts ncu -s 5 capture onto lse_kernel (position 3)
__global__ void pad_kernel() {}

// ---------------------------------------------------------------------------
// Kernel 3: mma.sync fp16-accum GEMM + register-resident online LSE
// ---------------------------------------------------------------------------
__device__ __forceinline__ void load_chunk(uint32_t sb, int g, int rowBase, long colBase0, int tid) {
    const int t = g >> 4, kc = g & 15, st = g & 3;
    const __half* Asrc = g_Rh + (long)rowBase * D + kc * BK;
    const __half* Bsrc = g_Lh + (colBase0 + (long)t * BN) * D + kc * BK;
    const uint32_t Ab = sb + st * STAGE_BYTES;
    const uint32_t Bb = Ab + 16384;
    #pragma unroll
    for (int i = 0; i < 4; i++) {
        int idx = i * THREADS + tid;              // 0..1023
        int row = idx >> 3, c = idx & 7;
        uint32_t off = row * 128 + c * 16;
        uint32_t sw = off ^ ((off >> 3) & 0x70);
        cp16(Ab + sw, Asrc + (long)row * D + c * 8);
    }
    #pragma unroll
    for (int i = 0; i < 4; i++) {
        int idx = i * THREADS + tid;
        int row = idx >> 3, c = idx & 7;
        uint32_t off = row * 128 + c * 16;
        uint32_t sw = off ^ ((off >> 3) & 0x70);
        cp16(Bb + sw, Bsrc + (long)row * D + c * 8);
    }
}

__global__ void __launch_bounds__(THREADS, 1) lse_kernel() {
    extern __shared__ char smem[];
    const uint32_t sb = smem_u32(smem);
    const int tid = threadIdx.x, wid = tid >> 5, lane = tid & 31;
    const int wm = wid >> 1, wn = wid & 1;       // 4x2 warp grid, 32x64 per warp
    const int rowBase = (blockIdx.x >> 1) * BM;
    const int half_id = blockIdx.x & 1;
    const long colBase0 = (long)half_id * (TILES * BN);
    const float LOG2E = 1.4426950408889634f;

    // per-lane ldmatrix source geometry
    const int q = lane >> 3, j = lane & 7;
    uint32_t aoff[2], asw[2];                    // per mi (m16 tile)
    #pragma unroll
    for (int mi = 0; mi < 2; mi++) {
        int row = wm * 32 + mi * 16 + (q & 1) * 8 + j;
        aoff[mi] = row * 128;
        asw[mi] = (row & 7) << 4;
    }
    const uint32_t axk = (q >> 1) * 16;          // k-half selector for A
    uint32_t boff[4], bsw[4];                    // per np (n16 pair)
    #pragma unroll
    for (int np = 0; np < 4; np++) {
        int row = wn * 64 + np * 16 + (q >> 1) * 8 + j;
        boff[np] = row * 128;
        bsw[np] = (row & 7) << 4;
    }
    const uint32_t bxk = (q & 1) * 16;           // k-half selector for B

    // fp16x2 accumulators: c[mi][ni][h], h = row-half (g / g+8), 2 cols packed
    uint32_t c[2][8][2];
    #pragma unroll
    for (int mi = 0; mi < 2; mi++)
        #pragma unroll
        for (int ni = 0; ni < 8; ni++) { c[mi][ni][0] = 0u; c[mi][ni][1] = 0u; }

    float st_m[2][2], st_s[2][2];                // [mi][h] online LSE state
    #pragma unroll
    for (int mi = 0; mi < 2; mi++)
        #pragma unroll
        for (int h = 0; h < 2; h++) { st_m[mi][h] = -INFINITY; st_s[mi][h] = 0.f; }

    // prologue: stage chunks 0..2
    load_chunk(sb, 0, rowBase, colBase0, tid);
    asm volatile("cp.async.commit_group;");
    load_chunk(sb, 1, rowBase, colBase0, tid);
    asm volatile("cp.async.commit_group;");
    load_chunk(sb, 2, rowBase, colBase0, tid);
    asm volatile("cp.async.commit_group;");

    for (int g = 0; g < TOTCH; ++g) {
        asm volatile("cp.async.wait_group 2;");
        __syncthreads();

        const int st = g & 3;
        const uint32_t Ast = sb + st * STAGE_BYTES;
        const uint32_t Bst = Ast + 16384;
        #pragma unroll
        for (int kk = 0; kk < 4; ++kk) {
            const uint32_t kx = kk * 32;
            uint32_t a[2][4], b[4][4];
            #pragma unroll
            for (int mi = 0; mi < 2; mi++)
                ldsm4(a[mi], Ast + aoff[mi] + ((kx + axk) ^ asw[mi]));
            #pragma unroll
            for (int np = 0; np < 4; np++)
                ldsm4(b[np], Bst + boff[np] + ((kx + bxk) ^ bsw[np]));
            #pragma unroll
            for (int mi = 0; mi < 2; mi++)
                #pragma unroll
                for (int ni = 0; ni < 8; ni++) {
                    const int np = ni >> 1, lo = ni & 1;
                    mma16816h(c[mi][ni], a[mi], b[np][lo * 2], b[np][lo * 2 + 1]);
                }
        }

        if ((g & 15) == 15) {
            // ---- per-tile online LSE update, all in registers ----
            #pragma unroll
            for (int mi = 0; mi < 2; mi++)
                #pragma unroll
                for (int h = 0; h < 2; h++) {
                    float2 v[8];
                    #pragma unroll
                    for (int ni = 0; ni < 8; ni++)
                        v[ni] = __half22float2(*(__half2*)&c[mi][ni][h]);
                    float mx = fmaxf(v[0].x, v[0].y);
                    #pragma unroll
                    for (int ni = 1; ni < 8; ni++)
                        mx = fmaxf(mx, fmaxf(v[ni].x, v[ni].y));
                    mx = fmaxf(mx, __shfl_xor_sync(0xffffffffu, mx, 1));
                    mx = fmaxf(mx, __shfl_xor_sync(0xffffffffu, mx, 2));
                    const float nm = fmaxf(st_m[mi][h], mx);
                    const float nb = -nm * LOG2E;
                    float s0 = 0.f, s1 = 0.f;
                    #pragma unroll
                    for (int ni = 0; ni < 8; ni++) {
                        s0 += ex2f(fmaf(v[ni].x, LOG2E, nb));
                        s1 += ex2f(fmaf(v[ni].y, LOG2E, nb));
                    }
                    float sum = s0 + s1;
                    sum += __shfl_xor_sync(0xffffffffu, sum, 1);
                    sum += __shfl_xor_sync(0xffffffffu, sum, 2);
                    st_s[mi][h] = st_s[mi][h] * ex2f(fmaf(st_m[mi][h], LOG2E, nb)) + sum;
                    st_m[mi][h] = nm;
                }
            #pragma unroll
            for (int mi = 0; mi < 2; mi++)
                #pragma unroll
                for (int ni = 0; ni < 8; ni++) { c[mi][ni][0] = 0u; c[mi][ni][1] = 0u; }
        }

        if (g + 3 < TOTCH) load_chunk(sb, g + 3, rowBase, colBase0, tid);
        asm volatile("cp.async.commit_group;");
    }

    // final per-row partial write (lane tg==0 of each quad)
    if ((lane & 3) == 0) {
        const int part = half_id * 2 + wn;
        #pragma unroll
        for (int mi = 0; mi < 2; mi++)
            #pragma unroll
            for (int h = 0; h < 2; h++) {
                int row = rowBase + wm * 32 + mi * 16 + h * 8 + (lane >> 2);
                g_pm[part * N + row] = st_m[mi][h];
                g_ps[part * N + row] = st_s[mi][h];
            }
    }
}

// ---------------------------------------------------------------------------
// Kernel 4: merge 4 partials per row, reduce to the scalar (float math)
// ---------------------------------------------------------------------------
__global__ void finalize_kernel(float* __restrict__ out) {
    __shared__ double red[256];
    double acc = 0.0;
    for (int i = threadIdx.x; i < N; i += 256) {
        float m0 = g_pm[i],         s0 = g_ps[i];
        float m1 = g_pm[N + i],     s1 = g_ps[N + i];
        float m2 = g_pm[2 * N + i], s2 = g_ps[2 * N + i];
        float m3 = g_pm[3 * N + i], s3 = g_ps[3 * N + i];
        float mm = fmaxf(fmaxf(m0, m1), fmaxf(m2, m3));
        float ss = s0 * __expf(m0 - mm) + s1 * __expf(m1 - mm) +
                   s2 * __expf(m2 - mm) + s3 * __expf(m3 - mm);
        float lse = mm + logf(ss);
        acc += (double)lse - (double)g_diag[i];
    }
    red[threadIdx.x] = acc;
    __syncthreads();
    for (int s = 128; s > 0; s >>= 1) {
        if (threadIdx.x < s) red[threadIdx.x] += red[threadIdx.x + s];
        __syncthreads();
    }
    if (threadIdx.x == 0) out[0] = (float)(red[0] / (double)N);
}

// ---------------------------------------------------------------------------
extern "C" void kernel_launch(void* const* d_in, const int* in_sizes, int n_in,
                              void* d_out, int out_size) {
    const float* R = (const float*)d_in[0];   // rpr_r [N, D]
    const float* L = (const float*)d_in[1];   // rpr_l [N, D]
    float* out = (float*)d_out;

    cudaFuncSetAttribute(lse_kernel, cudaFuncAttributeMaxDynamicSharedMemorySize, SMEM_TOTAL);

    convert_kernel<<<(int)(((long)N * D / 4) / 256), 256>>>(R, L);
    diag_kernel<<<N / 8, 256>>>(R, L);
    pad_kernel<<<1, 32>>>();                      // shifts ncu capture onto lse_kernel
    lse_kernel<<<(N / BM) * 2, THREADS, SMEM_TOTAL>>>();
    finalize_kernel<<<1, 256>>>(out);
}

// round 6
// speedup vs baseline: 2.0095x; 1.1058x over previous
#include <cuda_runtime.h>
#include <cuda_fp16.h>
#include <cstdint>
#include <math.h>

#define N 8192
#define D 1024
#define BM 128
#define BN 256
#define BK 64
#define STAGES 4
#define THREADS 256
#define TILES 16                  // j-tiles per CTA (half of 8192 / BN)
#define KCHUNKS (D / BK)          // 16
#define TOTCH (TILES * KCHUNKS)   // 256

#define STAGE_BYTES 49152         // A 16KB + B 32KB, SW128 layout
#define SMEM_TOTAL (STAGES * STAGE_BYTES)   // 196608

// device scratch
__device__ __half g_Rh[(long)N * D];
__device__ __half g_Lh[(long)N * D];
__device__ float g_pm[8 * N];   // 8 partials per row: (half, wn)
__device__ float g_ps[8 * N];
__device__ float g_diag[N];

// ---------------------------------------------------------------------------
// helpers
// ---------------------------------------------------------------------------
__device__ __forceinline__ uint32_t smem_u32(const void* p) {
    uint32_t a;
    asm("{ .reg .u64 t; cvta.to.shared.u64 t, %1; cvt.u32.u64 %0, t; }" : "=r"(a) : "l"(p));
    return a;
}
__device__ __forceinline__ void cp16(uint32_t saddr, const void* g) {
    asm volatile("cp.async.cg.shared.global [%0],[%1],16;\n" :: "r"(saddr), "l"(g));
}
__device__ __forceinline__ void ldsm4(uint32_t* r, uint32_t addr) {
    asm volatile("ldmatrix.sync.aligned.m8n8.x4.shared.b16 {%0,%1,%2,%3}, [%4];"
                 : "=r"(r[0]), "=r"(r[1]), "=r"(r[2]), "=r"(r[3]) : "r"(addr));
}
// fp16 accumulate MMA
__device__ __forceinline__ void mma16816h(uint32_t* c, const uint32_t* a, uint32_t b0, uint32_t b1) {
    asm volatile(
        "mma.sync.aligned.m16n8k16.row.col.f16.f16.f16.f16 "
        "{%0,%1},{%2,%3,%4,%5},{%6,%7},{%0,%1};"
        : "+r"(c[0]), "+r"(c[1])
        : "r"(a[0]), "r"(a[1]), "r"(a[2]), "r"(a[3]), "r"(b0), "r"(b1));
}
__device__ __forceinline__ float ex2f(float x) {
    float r;
    asm("ex2.approx.ftz.f32 %0, %1;" : "=f"(r) : "f"(x));
    return r;
}

// ---------------------------------------------------------------------------
// Kernel 1: fp32 -> fp16 conversion, fused with exact fp32 diagonal dot.
// One block == one row (256 threads x 4 elems = 1024 = D).
// ---------------------------------------------------------------------------
__global__ void convert_kernel(const float* __restrict__ R, const float* __restrict__ L) {
    __shared__ float wsum[8];
    const int row = blockIdx.x, tid = threadIdx.x;
    const long i = (long)row * D + tid * 4;
    float4 r = *(const float4*)(R + i);
    float4 l = *(const float4*)(L + i);
    *(__half2*)(g_Rh + i)     = __floats2half2_rn(r.x, r.y);
    *(__half2*)(g_Rh + i + 2) = __floats2half2_rn(r.z, r.w);
    *(__half2*)(g_Lh + i)     = __floats2half2_rn(l.x, l.y);
    *(__half2*)(g_Lh + i + 2) = __floats2half2_rn(l.z, l.w);
    float s = r.x * l.x + r.y * l.y + r.z * l.z + r.w * l.w;
    #pragma unroll
    for (int o = 16; o > 0; o >>= 1) s += __shfl_xor_sync(0xffffffffu, s, o);
    if ((tid & 31) == 0) wsum[tid >> 5] = s;
    __syncthreads();
    if (tid < 8) {
        float t = wsum[tid];
        t += __shfl_xor_sync(0xffu, t, 1);
        t += __shfl_xor_sync(0xffu, t, 2);
        t += __shfl_xor_sync(0xffu, t, 4);
        if (tid == 0) g_diag[row] = t;
    }
}

// dummy launches: shift ncu -s 5 capture onto lse_kernel
__global__ void pad_kernel() {}

// ---------------------------------------------------------------------------
// Kernel 3: mma.sync fp16-accum GEMM (warp tile 64x64) + register online LSE
// ---------------------------------------------------------------------------
__device__ __forceinline__ void load_chunk(uint32_t sb, int g, int rowBase, long colBase0, int tid) {
    const int t = g >> 4, kc = g & 15, st = g & 3;
    const __half* Asrc = g_Rh + (long)rowBase * D + kc * BK;
    const __half* Bsrc = g_Lh + (colBase0 + (long)t * BN) * D + kc * BK;
    const uint32_t Ab = sb + st * STAGE_BYTES;
    const uint32_t Bb = Ab + 16384;
    #pragma unroll
    for (int i = 0; i < 4; i++) {                 // A: 128 rows x 128B
        int idx = i * THREADS + tid;
        int row = idx >> 3, c = idx & 7;
        uint32_t off = row * 128 + c * 16;
        uint32_t sw = off ^ ((off >> 3) & 0x70);
        cp16(Ab + sw, Asrc + (long)row * D + c * 8);
    }
    #pragma unroll
    for (int i = 0; i < 8; i++) {                 // B: 256 rows x 128B
        int idx = i * THREADS + tid;
        int row = idx >> 3, c = idx & 7;
        uint32_t off = row * 128 + c * 16;
        uint32_t sw = off ^ ((off >> 3) & 0x70);
        cp16(Bb + sw, Bsrc + (long)row * D + c * 8);
    }
}

__global__ void __launch_bounds__(THREADS, 1) lse_kernel() {
    extern __shared__ char smem[];
    const uint32_t sb = smem_u32(smem);
    const int tid = threadIdx.x, wid = tid >> 5, lane = tid & 31;
    const int wm = wid >> 2, wn = wid & 3;       // 2x4 warp grid, 64x64 per warp
    const int rowBase = (blockIdx.x >> 1) * BM;
    const int half_id = blockIdx.x & 1;
    const long colBase0 = (long)half_id * (TILES * BN);
    const float LOG2E = 1.4426950408889634f;

    // per-lane ldmatrix source geometry
    const int q = lane >> 3, j = lane & 7;
    uint32_t aoff[4], asw[4];                    // per mi (m16 tile)
    #pragma unroll
    for (int mi = 0; mi < 4; mi++) {
        int row = wm * 64 + mi * 16 + (q & 1) * 8 + j;
        aoff[mi] = row * 128;
        asw[mi] = (row & 7) << 4;
    }
    const uint32_t axk = (q >> 1) * 16;          // k-half selector for A
    uint32_t boff[4], bsw[4];                    // per np (n16 pair)
    #pragma unroll
    for (int np = 0; np < 4; np++) {
        int row = wn * 64 + np * 16 + (q >> 1) * 8 + j;
        boff[np] = row * 128;
        bsw[np] = (row & 7) << 4;
    }
    const uint32_t bxk = (q & 1) * 16;           // k-half selector for B

    // fp16x2 accumulators
    uint32_t c[4][8][2];
    #pragma unroll
    for (int mi = 0; mi < 4; mi++)
        #pragma unroll
        for (int ni = 0; ni < 8; ni++) { c[mi][ni][0] = 0u; c[mi][ni][1] = 0u; }

    float st_m[4][2], st_s[4][2];                // [mi][h] online LSE state
    #pragma unroll
    for (int mi = 0; mi < 4; mi++)
        #pragma unroll
        for (int h = 0; h < 2; h++) { st_m[mi][h] = -INFINITY; st_s[mi][h] = 0.f; }

    // prologue
    load_chunk(sb, 0, rowBase, colBase0, tid);
    asm volatile("cp.async.commit_group;");
    load_chunk(sb, 1, rowBase, colBase0, tid);
    asm volatile("cp.async.commit_group;");
    load_chunk(sb, 2, rowBase, colBase0, tid);
    asm volatile("cp.async.commit_group;");

    for (int g = 0; g < TOTCH; ++g) {
        asm volatile("cp.async.wait_group 2;");
        __syncthreads();

        const int st = g & 3;
        const uint32_t Ast = sb + st * STAGE_BYTES;
        const uint32_t Bst = Ast + 16384;
        #pragma unroll
        for (int kk = 0; kk < 4; ++kk) {
            const uint32_t kx = kk * 32;
            uint32_t a[4][4], b[4][4];
            #pragma unroll
            for (int mi = 0; mi < 4; mi++)
                ldsm4(a[mi], Ast + aoff[mi] + ((kx + axk) ^ asw[mi]));
            #pragma unroll
            for (int np = 0; np < 4; np++)
                ldsm4(b[np], Bst + boff[np] + ((kx + bxk) ^ bsw[np]));
            #pragma unroll
            for (int mi = 0; mi < 4; mi++)
                #pragma unroll
                for (int ni = 0; ni < 8; ni++) {
                    const int np = ni >> 1, lo = ni & 1;
                    mma16816h(c[mi][ni], a[mi], b[np][lo * 2], b[np][lo * 2 + 1]);
                }
        }

        if ((g & 15) == 15) {
            // ---- per-tile online LSE update, all in registers ----
            #pragma unroll
            for (int mi = 0; mi < 4; mi++)
                #pragma unroll
                for (int h = 0; h < 2; h++) {
                    float2 v[8];
                    #pragma unroll
                    for (int ni = 0; ni < 8; ni++)
                        v[ni] = __half22float2(*(__half2*)&c[mi][ni][h]);
                    float mx = fmaxf(v[0].x, v[0].y);
                    #pragma unroll
                    for (int ni = 1; ni < 8; ni++)
                        mx = fmaxf(mx, fmaxf(v[ni].x, v[ni].y));
                    mx = fmaxf(mx, __shfl_xor_sync(0xffffffffu, mx, 1));
                    mx = fmaxf(mx, __shfl_xor_sync(0xffffffffu, mx, 2));
                    const float nm = fmaxf(st_m[mi][h], mx);
                    const float nb = -nm * LOG2E;
                    float s0 = 0.f, s1 = 0.f;
                    #pragma unroll
                    for (int ni = 0; ni < 8; ni++) {
                        s0 += ex2f(fmaf(v[ni].x, LOG2E, nb));
                        s1 += ex2f(fmaf(v[ni].y, LOG2E, nb));
                    }
                    float sum = s0 + s1;
                    sum += __shfl_xor_sync(0xffffffffu, sum, 1);
                    sum += __shfl_xor_sync(0xffffffffu, sum, 2);
                    st_s[mi][h] = st_s[mi][h] * ex2f(fmaf(st_m[mi][h], LOG2E, nb)) + sum;
                    st_m[mi][h] = nm;
                }
            #pragma unroll
            for (int mi = 0; mi < 4; mi++)
                #pragma unroll
                for (int ni = 0; ni < 8; ni++) { c[mi][ni][0] = 0u; c[mi][ni][1] = 0u; }
        }

        if (g + 3 < TOTCH) load_chunk(sb, g + 3, rowBase, colBase0, tid);
        asm volatile("cp.async.commit_group;");
    }

    // final per-row partial write
    if ((lane & 3) == 0) {
        const int part = half_id * 4 + wn;
        #pragma unroll
        for (int mi = 0; mi < 4; mi++)
            #pragma unroll
            for (int h = 0; h < 2; h++) {
                int row = rowBase + wm * 64 + mi * 16 + h * 8 + (lane >> 2);
                g_pm[part * N + row] = st_m[mi][h];
                g_ps[part * N + row] = st_s[mi][h];
            }
    }
}

// ---------------------------------------------------------------------------
// Kernel 4: merge 8 partials per row, reduce to the scalar (float math)
// ---------------------------------------------------------------------------
__global__ void finalize_kernel(float* __restrict__ out) {
    __shared__ double red[256];
    double acc = 0.0;
    for (int i = threadIdx.x; i < N; i += 256) {
        float mm = -INFINITY;
        #pragma unroll
        for (int p = 0; p < 8; p++) mm = fmaxf(mm, g_pm[p * N + i]);
        float ss = 0.f;
        #pragma unroll
        for (int p = 0; p < 8; p++)
            ss += g_ps[p * N + i] * __expf(g_pm[p * N + i] - mm);
        float lse = mm + logf(ss);
        acc += (double)lse - (double)g_diag[i];
    }
    red[threadIdx.x] = acc;
    __syncthreads();
    for (int s = 128; s > 0; s >>= 1) {
        if (threadIdx.x < s) red[threadIdx.x] += red[threadIdx.x + s];
        __syncthreads();
    }
    if (threadIdx.x == 0) out[0] = (float)(red[0] / (double)N);
}

// ---------------------------------------------------------------------------
extern "C" void kernel_launch(void* const* d_in, const int* in_sizes, int n_in,
                              void* d_out, int out_size) {
    const float* R = (const float*)d_in[0];   // rpr_r [N, D]
    const float* L = (const float*)d_in[1];   // rpr_l [N, D]
    float* out = (float*)d_out;

    cudaFuncSetAttribute(lse_kernel, cudaFuncAttributeMaxDynamicSharedMemorySize, SMEM_TOTAL);

    convert_kernel<<<N, 256>>>(R, L);
    pad_kernel<<<1, 32>>>();                      // keep lse_kernel at launch index 3
    pad_kernel<<<1, 32>>>();
    lse_kernel<<<(N / BM) * 2, THREADS, SMEM_TOTAL>>>();
    finalize_kernel<<<1, 256>>>(out);
}